// round 3
// baseline (speedup 1.0000x reference)
#include <cuda_runtime.h>

#define B_TOTAL   131072
#define T_STEPS   7
#define F_IN      60
#define UNITS     256
#define NCOLS     1024      // 4 * UNITS
#define BM        64        // batch rows per CTA
#define SX        68        // x smem row stride; 68%32==4 -> conflict free
#define SH        260       // h smem row stride; 260%32==4 -> conflict free
#define SC        257       // c smem row stride; 257%32==1 -> near conflict free
#define NTHREADS  256       // 8 warps: 2 (M) x 4 (N)

__device__ __forceinline__ unsigned cvt_tf32(float x) {
    unsigned r;
    asm("cvt.rna.tf32.f32 %0, %1;" : "=r"(r) : "f"(x));
    return r;
}

__device__ __forceinline__ void mma8(float (&c)[4], const unsigned (&a)[4],
                                     unsigned b0, unsigned b1) {
    asm volatile(
        "mma.sync.aligned.m16n8k8.row.col.f32.tf32.tf32.f32 "
        "{%0,%1,%2,%3}, {%4,%5,%6,%7}, {%8,%9}, {%0,%1,%2,%3};\n"
        : "+f"(c[0]), "+f"(c[1]), "+f"(c[2]), "+f"(c[3])
        : "r"(a[0]), "r"(a[1]), "r"(a[2]), "r"(a[3]), "r"(b0), "r"(b1));
}

__device__ __forceinline__ float sigmoidf_(float x) {
    return __fdividef(1.0f, 1.0f + __expf(-x));
}
__device__ __forceinline__ float tanhf_(float x) {
    return 1.0f - __fdividef(2.0f, __expf(2.0f * x) + 1.0f);
}

// acc[2][4][4] += A[64 x KTOT](tf32, smem) * B[KTOT x cols](fp32 global, hi/lo tf32 split).
// CLAMP60: x@W phase; A cols 60..63 are zero-padded, clamp OOB W row reads to row 0.
template <int KTOT, bool CLAMP60>
__device__ __forceinline__ void gemm_phase(
    float (&acc)[2][4][4], const float* __restrict__ As, int aStride,
    const float* __restrict__ Bg, const int (&physN)[4], int wm, int lane)
{
    const int q  = lane & 3;
    const int rA = lane >> 2;
    const int arowBase = wm * 32 + rA;

    float bnxt[4][2];
    {
        int kb0 = q, kb1 = q + 4;
        if (CLAMP60) { kb0 = (kb0 < 60) ? kb0 : 0; kb1 = (kb1 < 60) ? kb1 : 0; }
        const float* p0 = Bg + kb0 * NCOLS;
        const float* p1 = Bg + kb1 * NCOLS;
        #pragma unroll
        for (int nt = 0; nt < 4; ++nt) {
            bnxt[nt][0] = p0[physN[nt]];
            bnxt[nt][1] = p1[physN[nt]];
        }
    }

    #pragma unroll 4
    for (int k0 = 0; k0 < KTOT; k0 += 8) {
        float bcur[4][2];
        #pragma unroll
        for (int nt = 0; nt < 4; ++nt) { bcur[nt][0] = bnxt[nt][0]; bcur[nt][1] = bnxt[nt][1]; }

        if (k0 + 8 < KTOT) {   // prefetch next iteration's B
            int kb0 = k0 + 8 + q, kb1 = kb0 + 4;
            if (CLAMP60) { kb0 = (kb0 < 60) ? kb0 : 0; kb1 = (kb1 < 60) ? kb1 : 0; }
            const float* p0 = Bg + kb0 * NCOLS;
            const float* p1 = Bg + kb1 * NCOLS;
            #pragma unroll
            for (int nt = 0; nt < 4; ++nt) {
                bnxt[nt][0] = p0[physN[nt]];
                bnxt[nt][1] = p1[physN[nt]];
            }
        }

        unsigned a[2][4];
        #pragma unroll
        for (int mt = 0; mt < 2; ++mt) {
            const float* ap = As + (arowBase + mt * 16) * aStride + k0 + q;
            a[mt][0] = __float_as_uint(ap[0]);
            a[mt][1] = __float_as_uint(ap[8 * aStride]);
            a[mt][2] = __float_as_uint(ap[4]);
            a[mt][3] = __float_as_uint(ap[8 * aStride + 4]);
        }

        #pragma unroll
        for (int nt = 0; nt < 4; ++nt) {
            unsigned bh0 = cvt_tf32(bcur[nt][0]);
            unsigned bh1 = cvt_tf32(bcur[nt][1]);
            unsigned bl0 = cvt_tf32(bcur[nt][0] - __uint_as_float(bh0));
            unsigned bl1 = cvt_tf32(bcur[nt][1] - __uint_as_float(bh1));
            mma8(acc[0][nt], a[0], bh0, bh1);
            mma8(acc[1][nt], a[1], bh0, bh1);
            mma8(acc[0][nt], a[0], bl0, bl1);
            mma8(acc[1][nt], a[1], bl0, bl1);
        }
    }
}

__global__ void __launch_bounds__(NTHREADS, 1)
lstm_enc_kernel(const float* __restrict__ xg, const float* __restrict__ Wg,
                const float* __restrict__ Ug, const float* __restrict__ bg,
                float* __restrict__ out)
{
    extern __shared__ float smem[];
    float* xs = smem;                              // [BM][SX]
    float* hs = smem + BM * SX;                    // [2][BM][SH] double buffered
    float* cs = smem + BM * SX + 2 * BM * SH;      // [BM][SC] cell state

    const int tid  = threadIdx.x;
    const int lane = tid & 31;
    const int warp = tid >> 5;
    const int wm   = warp >> 2;
    const int wn   = warp & 3;
    const int q    = lane & 3;
    const int rA   = lane >> 2;
    const int row0 = blockIdx.x * BM;
    const bool evenT = ((lane & 1) == 0);

    // zero-init cell state (visible after first __syncthreads)
    for (int idx = tid; idx < BM * SC; idx += NTHREADS) cs[idx] = 0.0f;

    for (int t = 0; t < T_STEPS; ++t) {
        __syncthreads();

        // stage x_t (tf32-rounded)
        for (int idx = tid; idx < BM * F_IN; idx += NTHREADS) {
            int row = idx / F_IN;
            int col = idx - row * F_IN;
            float v = xg[(size_t)(row0 + row) * (T_STEPS * F_IN) + t * F_IN + col];
            xs[row * SX + col] = __uint_as_float(cvt_tf32(v));
        }
        for (int idx = tid; idx < BM * 4; idx += NTHREADS) {
            int row = idx >> 2;
            xs[row * SX + 60 + (idx & 3)] = 0.0f;
        }
        __syncthreads();

        const int rb = t & 1, wb = rb ^ 1;
        const float* hrd = hs + rb * (BM * SH);
        float*       hwr = hs + wb * (BM * SH);

        for (int ch = 0; ch < 8; ++ch) {
            const int u_base = ch * 32;

            int physN[4];
            #pragma unroll
            for (int nt = 0; nt < 4; ++nt) {
                int l = wn * 32 + nt * 8 + rA;
                physN[nt] = (l & 3) * UNITS + u_base + (l >> 2);
            }

            float acc[2][4][4];
            #pragma unroll
            for (int nt = 0; nt < 4; ++nt) {
                int l0 = wn * 32 + nt * 8 + 2 * q;
                int p0 = (l0 & 3) * UNITS + u_base + (l0 >> 2);
                int l1 = l0 + 1;
                int p1 = (l1 & 3) * UNITS + u_base + (l1 >> 2);
                float b0 = bg[p0], b1 = bg[p1];
                acc[0][nt][0] = b0; acc[0][nt][1] = b1; acc[0][nt][2] = b0; acc[0][nt][3] = b1;
                acc[1][nt][0] = b0; acc[1][nt][1] = b1; acc[1][nt][2] = b0; acc[1][nt][3] = b1;
            }

            gemm_phase<64, true>(acc, xs, SX, Wg, physN, wm, lane);
            if (t > 0)
                gemm_phase<256, false>(acc, hrd, SH, Ug, physN, wm, lane);

            // epilogue: gates -> c,h update (c lives in smem, keyed by (row, unit))
            #pragma unroll
            for (int mt = 0; mt < 2; ++mt) {
                const int rowL = wm * 32 + mt * 16 + rA;
                #pragma unroll
                for (int nt = 0; nt < 4; ++nt) {
                    const int unit = u_base + wn * 8 + nt * 2 + (q >> 1);
                    float z0 = acc[mt][nt][0], z1 = acc[mt][nt][1];
                    float z2 = acc[mt][nt][2], z3 = acc[mt][nt][3];
                    float p0 = __shfl_xor_sync(0xffffffffu, z0, 1);
                    float p2 = __shfl_xor_sync(0xffffffffu, z2, 1);
                    float tc0 = 0.0f, tc1 = 0.0f;
                    float cn0 = 0.0f, cn1 = 0.0f;
                    if (evenT) {
                        float c0 = cs[rowL * SC + unit];
                        float c1 = cs[(rowL + 8) * SC + unit];
                        float i0 = sigmoidf_(z0), f0 = sigmoidf_(z1), g0 = tanhf_(p0);
                        cn0 = f0 * c0 + i0 * g0;
                        tc0 = tanhf_(cn0);
                        float i1 = sigmoidf_(z2), f1 = sigmoidf_(z3), g1 = tanhf_(p2);
                        cn1 = f1 * c1 + i1 * g1;
                        tc1 = tanhf_(cn1);
                        cs[rowL * SC + unit]       = cn0;
                        cs[(rowL + 8) * SC + unit] = cn1;
                    }
                    float th0 = __shfl_xor_sync(0xffffffffu, tc0, 1);
                    float th1 = __shfl_xor_sync(0xffffffffu, tc1, 1);
                    if (!evenT) {
                        float o0 = sigmoidf_(z1), o1 = sigmoidf_(z3);
                        float h0 = o0 * th0, h1 = o1 * th1;
                        hwr[rowL * SH + unit]       = __uint_as_float(cvt_tf32(h0));
                        hwr[(rowL + 8) * SH + unit] = __uint_as_float(cvt_tf32(h1));
                        if (t == T_STEPS - 1) {
                            size_t g0i = (size_t)(row0 + rowL) * UNITS + unit;
                            size_t g1i = (size_t)(row0 + rowL + 8) * UNITS + unit;
                            const size_t HOFF = (size_t)B_TOTAL * UNITS;
                            out[g0i] = h0;          out[g1i] = h1;
                            out[HOFF + g0i] = h0;   out[HOFF + g1i] = h1;
                        }
                    } else if (t == T_STEPS - 1) {
                        const size_t COFF = 2 * (size_t)B_TOTAL * UNITS;
                        out[COFF + (size_t)(row0 + rowL) * UNITS + unit]     = cn0;
                        out[COFF + (size_t)(row0 + rowL + 8) * UNITS + unit] = cn1;
                    }
                }
            }
        }
    }
}

extern "C" void kernel_launch(void* const* d_in, const int* in_sizes, int n_in,
                              void* d_out, int out_size) {
    // Disambiguate inputs by element count (robust to any ordering):
    const float* x = nullptr;
    const float* W = nullptr;
    const float* U = nullptr;
    const float* b = nullptr;
    for (int i = 0; i < n_in; ++i) {
        switch (in_sizes[i]) {
            case B_TOTAL * T_STEPS * F_IN: x = (const float*)d_in[i]; break;
            case F_IN * NCOLS:             W = (const float*)d_in[i]; break;
            case UNITS * NCOLS:            U = (const float*)d_in[i]; break;
            case NCOLS:                    b = (const float*)d_in[i]; break;
            default: break;
        }
    }
    if (!x) x = (const float*)d_in[0];
    if (!W) W = (const float*)d_in[1];
    if (!U) U = (const float*)d_in[2];
    if (!b) b = (const float*)d_in[3];

    float* out = (float*)d_out;   // (h, h, c), each [B, UNITS]

    const int smem_bytes = (BM * SX + 2 * BM * SH + BM * SC) * (int)sizeof(float); // 216320
    cudaFuncSetAttribute(lstm_enc_kernel,
                         cudaFuncAttributeMaxDynamicSharedMemorySize, smem_bytes);

    lstm_enc_kernel<<<B_TOTAL / BM, NTHREADS, smem_bytes>>>(x, W, U, b, out);
}

// round 4
// speedup vs baseline: 2.6345x; 2.6345x over previous
#include <cuda_runtime.h>

#define B_TOTAL   131072
#define T_STEPS   7
#define F_IN      60
#define UNITS     256
#define NCOLS     1024      // 4 * UNITS
#define BM        64        // batch rows per CTA
#define SX        68        // x smem row stride; 68%32==4 -> conflict free
#define SH        260       // h smem row stride; 260%32==4 -> conflict free
#define SC        257       // c smem row stride
#define NTHREADS  256       // 8 warps: 2 (M) x 4 (N)

// Packed, fragment-ordered, hi/lo tf32-split weights (built once per launch by pack_kernel).
// Index: (ko * 1024 + Lp) * 4 + q  ->  uint4{ hi(k=ko*8+q), hi(k+4), lo(k), lo(k+4) }
// Lp is the "logical" column: phys = ((Lp&3... see P(Lp) below.
__device__ uint4 g_Wp[8  * NCOLS * 4];   // 512 KB  (K padded 60 -> 64 with zeros)
__device__ uint4 g_Up[32 * NCOLS * 4];   // 2 MB
__device__ float g_bp[NCOLS];            // bias permuted to logical order

__device__ __forceinline__ unsigned cvt_tf32(float x) {
    unsigned r;
    asm("cvt.rna.tf32.f32 %0, %1;" : "=r"(r) : "f"(x));
    return r;
}

// logical column -> physical column (gate-interleaved map used by the epilogue)
__device__ __forceinline__ int phys_col(int Lp) {
    int ch = Lp >> 7;          // 32-unit chunk
    int l  = Lp & 127;
    return ((l & 3) << 8) + (ch << 5) + (l >> 2);   // gate*256 + ch*32 + local_unit
}

__global__ void pack_kernel(const float* __restrict__ W,
                            const float* __restrict__ U,
                            const float* __restrict__ b) {
    int idx = blockIdx.x * blockDim.x + threadIdx.x;   // 0 .. 131071
    if (idx < 32 * NCOLS * 4) {
        int q  = idx & 3;
        int Lp = (idx >> 2) & (NCOLS - 1);
        int ko = idx >> 12;
        int p  = phys_col(Lp);
        float v0 = U[(ko * 8 + q) * NCOLS + p];
        float v1 = U[(ko * 8 + q + 4) * NCOLS + p];
        unsigned h0 = cvt_tf32(v0), h1 = cvt_tf32(v1);
        unsigned l0 = cvt_tf32(v0 - __uint_as_float(h0));
        unsigned l1 = cvt_tf32(v1 - __uint_as_float(h1));
        g_Up[idx] = make_uint4(h0, h1, l0, l1);
    }
    if (idx < 8 * NCOLS * 4) {
        int q  = idx & 3;
        int Lp = (idx >> 2) & (NCOLS - 1);
        int ko = idx >> 12;
        int p  = phys_col(Lp);
        int k0 = ko * 8 + q, k1 = k0 + 4;
        float v0 = (k0 < F_IN) ? W[k0 * NCOLS + p] : 0.0f;
        float v1 = (k1 < F_IN) ? W[k1 * NCOLS + p] : 0.0f;
        unsigned h0 = cvt_tf32(v0), h1 = cvt_tf32(v1);
        unsigned l0 = cvt_tf32(v0 - __uint_as_float(h0));
        unsigned l1 = cvt_tf32(v1 - __uint_as_float(h1));
        g_Wp[idx] = make_uint4(h0, h1, l0, l1);
    }
    if (idx < NCOLS) {
        g_bp[idx] = b[phys_col(idx)];
    }
}

__device__ __forceinline__ void mma8(float (&c)[4], const unsigned (&a)[4],
                                     unsigned b0, unsigned b1) {
    asm volatile(
        "mma.sync.aligned.m16n8k8.row.col.f32.tf32.tf32.f32 "
        "{%0,%1,%2,%3}, {%4,%5,%6,%7}, {%8,%9}, {%0,%1,%2,%3};\n"
        : "+f"(c[0]), "+f"(c[1]), "+f"(c[2]), "+f"(c[3])
        : "r"(a[0]), "r"(a[1]), "r"(a[2]), "r"(a[3]), "r"(b0), "r"(b1));
}

__device__ __forceinline__ float sigmoidf_(float x) {
    return __fdividef(1.0f, 1.0f + __expf(-x));
}
__device__ __forceinline__ float tanhf_(float x) {
    return 1.0f - __fdividef(2.0f, __expf(2.0f * x) + 1.0f);
}

// acc += A[64 x KOT*8](tf32, smem) * Bp (packed hi/lo tf32, coalesced LDG.128)
template <int KOT>
__device__ __forceinline__ void gemm_phase(
    float (&acc)[2][4][4], const float* __restrict__ As, int aStride,
    const uint4* __restrict__ Bp, int idxBase, int wm, int lane)
{
    const int q  = lane & 3;
    const int rA = lane >> 2;
    const int arowBase = wm * 32 + rA;

    uint4 bnxt[4];
    #pragma unroll
    for (int nt = 0; nt < 4; ++nt) bnxt[nt] = Bp[idxBase + nt * 32];

    #pragma unroll 4
    for (int ko = 0; ko < KOT; ++ko) {
        uint4 bcur[4];
        #pragma unroll
        for (int nt = 0; nt < 4; ++nt) bcur[nt] = bnxt[nt];
        if (ko + 1 < KOT) {
            #pragma unroll
            for (int nt = 0; nt < 4; ++nt)
                bnxt[nt] = Bp[idxBase + (ko + 1) * 4096 + nt * 32];
        }

        unsigned a[2][4];
        #pragma unroll
        for (int mt = 0; mt < 2; ++mt) {
            const float* ap = As + (arowBase + mt * 16) * aStride + ko * 8 + q;
            a[mt][0] = __float_as_uint(ap[0]);
            a[mt][1] = __float_as_uint(ap[8 * aStride]);
            a[mt][2] = __float_as_uint(ap[4]);
            a[mt][3] = __float_as_uint(ap[8 * aStride + 4]);
        }

        #pragma unroll
        for (int nt = 0; nt < 4; ++nt) {
            mma8(acc[0][nt], a[0], bcur[nt].x, bcur[nt].y);
            mma8(acc[1][nt], a[1], bcur[nt].x, bcur[nt].y);
            mma8(acc[0][nt], a[0], bcur[nt].z, bcur[nt].w);
            mma8(acc[1][nt], a[1], bcur[nt].z, bcur[nt].w);
        }
    }
}

__global__ void __launch_bounds__(NTHREADS, 1)
lstm_enc_kernel(const float* __restrict__ xg, float* __restrict__ out)
{
    extern __shared__ float smem[];
    float* xs = smem;                              // [BM][SX]
    float* hs = smem + BM * SX;                    // [2][BM][SH] double buffered
    float* cs = smem + BM * SX + 2 * BM * SH;      // [BM][SC] cell state

    const int tid  = threadIdx.x;
    const int lane = tid & 31;
    const int warp = tid >> 5;
    const int wm   = warp >> 2;
    const int wn   = warp & 3;
    const int q    = lane & 3;
    const int rA   = lane >> 2;
    const int row0 = blockIdx.x * BM;
    const bool evenT = ((lane & 1) == 0);

    for (int idx = tid; idx < BM * SC; idx += NTHREADS) cs[idx] = 0.0f;

    for (int t = 0; t < T_STEPS; ++t) {
        __syncthreads();

        // stage x_t (tf32-rounded), zero-pad cols 60..63
        for (int idx = tid; idx < BM * F_IN; idx += NTHREADS) {
            int row = idx / F_IN;
            int col = idx - row * F_IN;
            float v = xg[(size_t)(row0 + row) * (T_STEPS * F_IN) + t * F_IN + col];
            xs[row * SX + col] = __uint_as_float(cvt_tf32(v));
        }
        for (int idx = tid; idx < BM * 4; idx += NTHREADS) {
            int row = idx >> 2;
            xs[row * SX + 60 + (idx & 3)] = 0.0f;
        }
        __syncthreads();

        const int rb = t & 1, wb = rb ^ 1;
        const float* hrd = hs + rb * (BM * SH);
        float*       hwr = hs + wb * (BM * SH);

        for (int ch = 0; ch < 8; ++ch) {
            const int u_base = ch * 32;
            const int idxBase = ((ch * 128 + wn * 32 + rA) << 2) + q;

            // bias init (packed, coalesced / broadcast)
            float acc[2][4][4];
            const float2* bp2 = reinterpret_cast<const float2*>(g_bp);
            #pragma unroll
            for (int nt = 0; nt < 4; ++nt) {
                float2 bb = bp2[ch * 64 + wn * 16 + nt * 4 + q];
                acc[0][nt][0] = bb.x; acc[0][nt][1] = bb.y;
                acc[0][nt][2] = bb.x; acc[0][nt][3] = bb.y;
                acc[1][nt][0] = bb.x; acc[1][nt][1] = bb.y;
                acc[1][nt][2] = bb.x; acc[1][nt][3] = bb.y;
            }

            gemm_phase<8>(acc, xs, SX, g_Wp, idxBase, wm, lane);
            if (t > 0)
                gemm_phase<32>(acc, hrd, SH, g_Up, idxBase, wm, lane);

            // epilogue: gates -> c,h update
            #pragma unroll
            for (int mt = 0; mt < 2; ++mt) {
                const int rowL = wm * 32 + mt * 16 + rA;
                #pragma unroll
                for (int nt = 0; nt < 4; ++nt) {
                    const int unit = u_base + wn * 8 + nt * 2 + (q >> 1);
                    float z0 = acc[mt][nt][0], z1 = acc[mt][nt][1];
                    float z2 = acc[mt][nt][2], z3 = acc[mt][nt][3];
                    float p0 = __shfl_xor_sync(0xffffffffu, z0, 1);
                    float p2 = __shfl_xor_sync(0xffffffffu, z2, 1);
                    float tc0 = 0.0f, tc1 = 0.0f;
                    float cn0 = 0.0f, cn1 = 0.0f;
                    if (evenT) {
                        float c0 = cs[rowL * SC + unit];
                        float c1 = cs[(rowL + 8) * SC + unit];
                        float i0 = sigmoidf_(z0), f0 = sigmoidf_(z1), g0 = tanhf_(p0);
                        cn0 = f0 * c0 + i0 * g0;
                        tc0 = tanhf_(cn0);
                        float i1 = sigmoidf_(z2), f1 = sigmoidf_(z3), g1 = tanhf_(p2);
                        cn1 = f1 * c1 + i1 * g1;
                        tc1 = tanhf_(cn1);
                        cs[rowL * SC + unit]       = cn0;
                        cs[(rowL + 8) * SC + unit] = cn1;
                    }
                    float th0 = __shfl_xor_sync(0xffffffffu, tc0, 1);
                    float th1 = __shfl_xor_sync(0xffffffffu, tc1, 1);
                    if (!evenT) {
                        float o0 = sigmoidf_(z1), o1 = sigmoidf_(z3);
                        float h0 = o0 * th0, h1 = o1 * th1;
                        hwr[rowL * SH + unit]       = __uint_as_float(cvt_tf32(h0));
                        hwr[(rowL + 8) * SH + unit] = __uint_as_float(cvt_tf32(h1));
                        if (t == T_STEPS - 1) {
                            size_t g0i = (size_t)(row0 + rowL) * UNITS + unit;
                            size_t g1i = (size_t)(row0 + rowL + 8) * UNITS + unit;
                            const size_t HOFF = (size_t)B_TOTAL * UNITS;
                            out[g0i] = h0;          out[g1i] = h1;
                            out[HOFF + g0i] = h0;   out[HOFF + g1i] = h1;
                        }
                    } else if (t == T_STEPS - 1) {
                        const size_t COFF = 2 * (size_t)B_TOTAL * UNITS;
                        out[COFF + (size_t)(row0 + rowL) * UNITS + unit]     = cn0;
                        out[COFF + (size_t)(row0 + rowL + 8) * UNITS + unit] = cn1;
                    }
                }
            }
        }
    }
}

extern "C" void kernel_launch(void* const* d_in, const int* in_sizes, int n_in,
                              void* d_out, int out_size) {
    const float* x = nullptr;
    const float* W = nullptr;
    const float* U = nullptr;
    const float* b = nullptr;
    for (int i = 0; i < n_in; ++i) {
        switch (in_sizes[i]) {
            case B_TOTAL * T_STEPS * F_IN: x = (const float*)d_in[i]; break;
            case F_IN * NCOLS:             W = (const float*)d_in[i]; break;
            case UNITS * NCOLS:            U = (const float*)d_in[i]; break;
            case NCOLS:                    b = (const float*)d_in[i]; break;
            default: break;
        }
    }
    if (!x) x = (const float*)d_in[0];
    if (!W) W = (const float*)d_in[1];
    if (!U) U = (const float*)d_in[2];
    if (!b) b = (const float*)d_in[3];

    float* out = (float*)d_out;

    pack_kernel<<<512, 256>>>(W, U, b);

    const int smem_bytes = (BM * SX + 2 * BM * SH + BM * SC) * (int)sizeof(float); // 216320
    cudaFuncSetAttribute(lstm_enc_kernel,
                         cudaFuncAttributeMaxDynamicSharedMemorySize, smem_bytes);
    lstm_enc_kernel<<<B_TOTAL / BM, NTHREADS, smem_bytes>>>(x, out);
}

// round 5
// speedup vs baseline: 4.0757x; 1.5470x over previous
#include <cuda_runtime.h>

#define B_TOTAL   131072
#define T_STEPS   7
#define F_IN      60
#define UNITS     256
#define NCOLS     1024      // 4 * UNITS
#define BM        64        // batch rows per CTA
#define SX        68        // x smem row stride; 68%32==4 -> conflict free
#define SH        260       // h smem row stride; 260%32==4 -> conflict free
#define SC        257       // c smem row stride
#define NTHREADS  256       // 8 warps: 2 (M) x 4 (N)

// Packed, fragment-ordered tf32 weights (single precision pass; A-side tf32 rounding
// dominates the error budget, measured 2.17e-4 with exact B; adding B rounding ~ *sqrt(2)).
// Index: (ko2 * 1024 + Lp) * 4 + q -> uint4{ b(k), b(k+4), b(k+8), b(k+12) }, k = ko2*16+q.
__device__ uint4 g_Wp[4  * NCOLS * 4];   // 256 KB (K padded 60 -> 64 with zeros)
__device__ uint4 g_Up[16 * NCOLS * 4];   // 1 MB
__device__ float g_bp[NCOLS];            // bias permuted to logical order

__device__ __forceinline__ unsigned cvt_tf32(float x) {
    unsigned r;
    asm("cvt.rna.tf32.f32 %0, %1;" : "=r"(r) : "f"(x));
    return r;
}

// logical column -> physical column (gate-interleaved map used by the epilogue)
__device__ __forceinline__ int phys_col(int Lp) {
    int ch = Lp >> 7;
    int l  = Lp & 127;
    return ((l & 3) << 8) + (ch << 5) + (l >> 2);   // gate*256 + ch*32 + local_unit
}

__global__ void pack_kernel(const float* __restrict__ W,
                            const float* __restrict__ U,
                            const float* __restrict__ b) {
    int idx = blockIdx.x * blockDim.x + threadIdx.x;   // 0 .. 65535
    if (idx < 16 * NCOLS * 4) {
        int q   = idx & 3;
        int Lp  = (idx >> 2) & (NCOLS - 1);
        int ko2 = idx >> 12;
        int p   = phys_col(Lp);
        int k   = ko2 * 16 + q;
        g_Up[idx] = make_uint4(cvt_tf32(U[(k     ) * NCOLS + p]),
                               cvt_tf32(U[(k +  4) * NCOLS + p]),
                               cvt_tf32(U[(k +  8) * NCOLS + p]),
                               cvt_tf32(U[(k + 12) * NCOLS + p]));
    }
    if (idx < 4 * NCOLS * 4) {
        int q   = idx & 3;
        int Lp  = (idx >> 2) & (NCOLS - 1);
        int ko2 = idx >> 12;
        int p   = phys_col(Lp);
        int k   = ko2 * 16 + q;
        unsigned v0 = (k      < F_IN) ? cvt_tf32(W[(k     ) * NCOLS + p]) : 0u;
        unsigned v1 = (k +  4 < F_IN) ? cvt_tf32(W[(k +  4) * NCOLS + p]) : 0u;
        unsigned v2 = (k +  8 < F_IN) ? cvt_tf32(W[(k +  8) * NCOLS + p]) : 0u;
        unsigned v3 = (k + 12 < F_IN) ? cvt_tf32(W[(k + 12) * NCOLS + p]) : 0u;
        g_Wp[idx] = make_uint4(v0, v1, v2, v3);
    }
    if (idx < NCOLS) {
        g_bp[idx] = b[phys_col(idx)];
    }
}

__device__ __forceinline__ void mma8(float (&c)[4], const unsigned (&a)[4],
                                     unsigned b0, unsigned b1) {
    asm volatile(
        "mma.sync.aligned.m16n8k8.row.col.f32.tf32.tf32.f32 "
        "{%0,%1,%2,%3}, {%4,%5,%6,%7}, {%8,%9}, {%0,%1,%2,%3};\n"
        : "+f"(c[0]), "+f"(c[1]), "+f"(c[2]), "+f"(c[3])
        : "r"(a[0]), "r"(a[1]), "r"(a[2]), "r"(a[3]), "r"(b0), "r"(b1));
}

__device__ __forceinline__ float sigmoidf_(float x) {
    return __fdividef(1.0f, 1.0f + __expf(-x));
}
__device__ __forceinline__ float tanhf_(float x) {
    return 1.0f - __fdividef(2.0f, __expf(2.0f * x) + 1.0f);
}

// acc += A[64 x KOT2*16](tf32, smem) * Bp (packed tf32, LDG.128, PDIST=2 ring prefetch)
template <int KOT2>
__device__ __forceinline__ void gemm_phase(
    float (&acc)[2][4][4], const float* __restrict__ As, int aStride,
    const uint4* __restrict__ Bp, int idxBase, int wm, int lane)
{
    const int q  = lane & 3;
    const int rA = lane >> 2;
    const int arowBase = wm * 32 + rA;

    uint4 bbuf[2][4];
    #pragma unroll
    for (int p = 0; p < 2 && p < KOT2; ++p)
        #pragma unroll
        for (int nt = 0; nt < 4; ++nt)
            bbuf[p][nt] = Bp[idxBase + p * 4096 + nt * 32];

    #pragma unroll
    for (int ko2 = 0; ko2 < KOT2; ++ko2) {
        uint4 bcur[4];
        #pragma unroll
        for (int nt = 0; nt < 4; ++nt) bcur[nt] = bbuf[ko2 & 1][nt];

        if (ko2 + 2 < KOT2) {
            #pragma unroll
            for (int nt = 0; nt < 4; ++nt)
                bbuf[ko2 & 1][nt] = Bp[idxBase + (ko2 + 2) * 4096 + nt * 32];
        }

        // A fragments for k-bases ko2*16 and ko2*16+8
        unsigned a0[2][4], a1[2][4];
        #pragma unroll
        for (int mt = 0; mt < 2; ++mt) {
            const float* ap = As + (arowBase + mt * 16) * aStride + ko2 * 16 + q;
            a0[mt][0] = __float_as_uint(ap[0]);
            a0[mt][1] = __float_as_uint(ap[8 * aStride]);
            a0[mt][2] = __float_as_uint(ap[4]);
            a0[mt][3] = __float_as_uint(ap[8 * aStride + 4]);
            a1[mt][0] = __float_as_uint(ap[8]);
            a1[mt][1] = __float_as_uint(ap[8 * aStride + 8]);
            a1[mt][2] = __float_as_uint(ap[12]);
            a1[mt][3] = __float_as_uint(ap[8 * aStride + 12]);
        }

        #pragma unroll
        for (int nt = 0; nt < 4; ++nt) {
            mma8(acc[0][nt], a0[0], bcur[nt].x, bcur[nt].y);
            mma8(acc[1][nt], a0[1], bcur[nt].x, bcur[nt].y);
            mma8(acc[0][nt], a1[0], bcur[nt].z, bcur[nt].w);
            mma8(acc[1][nt], a1[1], bcur[nt].z, bcur[nt].w);
        }
    }
}

__global__ void __launch_bounds__(NTHREADS, 1)
lstm_enc_kernel(const float* __restrict__ xg, float* __restrict__ out)
{
    extern __shared__ float smem[];
    float* xs = smem;                              // [BM][SX]
    float* hs = smem + BM * SX;                    // [2][BM][SH] double buffered
    float* cs = smem + BM * SX + 2 * BM * SH;      // [BM][SC] cell state

    const int tid  = threadIdx.x;
    const int lane = tid & 31;
    const int warp = tid >> 5;
    const int wm   = warp >> 2;
    const int wn   = warp & 3;
    const int q    = lane & 3;
    const int rA   = lane >> 2;
    const int row0 = blockIdx.x * BM;
    const bool evenT = ((lane & 1) == 0);

    for (int idx = tid; idx < BM * SC; idx += NTHREADS) cs[idx] = 0.0f;

    for (int t = 0; t < T_STEPS; ++t) {
        __syncthreads();

        // stage x_t (tf32-rounded), zero-pad cols 60..63
        for (int idx = tid; idx < BM * F_IN; idx += NTHREADS) {
            int row = idx / F_IN;
            int col = idx - row * F_IN;
            float v = xg[(size_t)(row0 + row) * (T_STEPS * F_IN) + t * F_IN + col];
            xs[row * SX + col] = __uint_as_float(cvt_tf32(v));
        }
        for (int idx = tid; idx < BM * 4; idx += NTHREADS) {
            int row = idx >> 2;
            xs[row * SX + 60 + (idx & 3)] = 0.0f;
        }
        __syncthreads();

        const int rb = t & 1, wb = rb ^ 1;
        const float* hrd = hs + rb * (BM * SH);
        float*       hwr = hs + wb * (BM * SH);

        for (int ch = 0; ch < 8; ++ch) {
            const int u_base = ch * 32;
            const int idxBase = ((ch * 128 + wn * 32 + rA) << 2) + q;

            float acc[2][4][4];
            const float2* bp2 = reinterpret_cast<const float2*>(g_bp);
            #pragma unroll
            for (int nt = 0; nt < 4; ++nt) {
                float2 bb = bp2[ch * 64 + wn * 16 + nt * 4 + q];
                acc[0][nt][0] = bb.x; acc[0][nt][1] = bb.y;
                acc[0][nt][2] = bb.x; acc[0][nt][3] = bb.y;
                acc[1][nt][0] = bb.x; acc[1][nt][1] = bb.y;
                acc[1][nt][2] = bb.x; acc[1][nt][3] = bb.y;
            }

            gemm_phase<4>(acc, xs, SX, g_Wp, idxBase, wm, lane);
            if (t > 0)
                gemm_phase<16>(acc, hrd, SH, g_Up, idxBase, wm, lane);

            // epilogue: gates -> c,h update
            #pragma unroll
            for (int mt = 0; mt < 2; ++mt) {
                const int rowL = wm * 32 + mt * 16 + rA;
                #pragma unroll
                for (int nt = 0; nt < 4; ++nt) {
                    const int unit = u_base + wn * 8 + nt * 2 + (q >> 1);
                    float z0 = acc[mt][nt][0], z1 = acc[mt][nt][1];
                    float z2 = acc[mt][nt][2], z3 = acc[mt][nt][3];
                    float p0 = __shfl_xor_sync(0xffffffffu, z0, 1);
                    float p2 = __shfl_xor_sync(0xffffffffu, z2, 1);
                    float tc0 = 0.0f, tc1 = 0.0f;
                    float cn0 = 0.0f, cn1 = 0.0f;
                    if (evenT) {
                        float c0 = cs[rowL * SC + unit];
                        float c1 = cs[(rowL + 8) * SC + unit];
                        float i0 = sigmoidf_(z0), f0 = sigmoidf_(z1), g0 = tanhf_(p0);
                        cn0 = f0 * c0 + i0 * g0;
                        tc0 = tanhf_(cn0);
                        float i1 = sigmoidf_(z2), f1 = sigmoidf_(z3), g1 = tanhf_(p2);
                        cn1 = f1 * c1 + i1 * g1;
                        tc1 = tanhf_(cn1);
                        cs[rowL * SC + unit]       = cn0;
                        cs[(rowL + 8) * SC + unit] = cn1;
                    }
                    float th0 = __shfl_xor_sync(0xffffffffu, tc0, 1);
                    float th1 = __shfl_xor_sync(0xffffffffu, tc1, 1);
                    if (!evenT) {
                        float o0 = sigmoidf_(z1), o1 = sigmoidf_(z3);
                        float h0 = o0 * th0, h1 = o1 * th1;
                        hwr[rowL * SH + unit]       = __uint_as_float(cvt_tf32(h0));
                        hwr[(rowL + 8) * SH + unit] = __uint_as_float(cvt_tf32(h1));
                        if (t == T_STEPS - 1) {
                            size_t g0i = (size_t)(row0 + rowL) * UNITS + unit;
                            size_t g1i = (size_t)(row0 + rowL + 8) * UNITS + unit;
                            const size_t HOFF = (size_t)B_TOTAL * UNITS;
                            out[g0i] = h0;          out[g1i] = h1;
                            out[HOFF + g0i] = h0;   out[HOFF + g1i] = h1;
                        }
                    } else if (t == T_STEPS - 1) {
                        const size_t COFF = 2 * (size_t)B_TOTAL * UNITS;
                        out[COFF + (size_t)(row0 + rowL) * UNITS + unit]     = cn0;
                        out[COFF + (size_t)(row0 + rowL + 8) * UNITS + unit] = cn1;
                    }
                }
            }
        }
    }
}

extern "C" void kernel_launch(void* const* d_in, const int* in_sizes, int n_in,
                              void* d_out, int out_size) {
    const float* x = nullptr;
    const float* W = nullptr;
    const float* U = nullptr;
    const float* b = nullptr;
    for (int i = 0; i < n_in; ++i) {
        switch (in_sizes[i]) {
            case B_TOTAL * T_STEPS * F_IN: x = (const float*)d_in[i]; break;
            case F_IN * NCOLS:             W = (const float*)d_in[i]; break;
            case UNITS * NCOLS:            U = (const float*)d_in[i]; break;
            case NCOLS:                    b = (const float*)d_in[i]; break;
            default: break;
        }
    }
    if (!x) x = (const float*)d_in[0];
    if (!W) W = (const float*)d_in[1];
    if (!U) U = (const float*)d_in[2];
    if (!b) b = (const float*)d_in[3];

    float* out = (float*)d_out;

    pack_kernel<<<256, 256>>>(W, U, b);

    const int smem_bytes = (BM * SX + 2 * BM * SH + BM * SC) * (int)sizeof(float); // 216320
    cudaFuncSetAttribute(lstm_enc_kernel,
                         cudaFuncAttributeMaxDynamicSharedMemorySize, smem_bytes);
    lstm_enc_kernel<<<B_TOTAL / BM, NTHREADS, smem_bytes>>>(x, out);
}

// round 6
// speedup vs baseline: 4.2121x; 1.0335x over previous
#include <cuda_runtime.h>

#define B_TOTAL   131072
#define T_STEPS   7
#define F_IN      60
#define UNITS     256
#define NCOLS     1024      // 4 * UNITS
#define BM        64        // batch rows per CTA
#define SX        68        // x smem row stride; 68%32==4 -> conflict free
#define SH        260       // h smem row stride; 260%32==4 -> conflict free
#define SC        257       // c smem row stride
#define NTHREADS  256       // 8 warps: 2 (M) x 4 (N)

// Packed, fragment-ordered tf32 weights.
// Index: (ko2 * 1024 + Lp) * 4 + q -> uint4{ b(k), b(k+4), b(k+8), b(k+12) }, k = ko2*16+q.
__device__ uint4 g_Wp[4  * NCOLS * 4];   // 256 KB (K padded 60 -> 64 with zeros)
__device__ uint4 g_Up[16 * NCOLS * 4];   // 1 MB
__device__ float g_bp[NCOLS];            // bias permuted to logical order

__device__ __forceinline__ unsigned cvt_tf32(float x) {
    unsigned r;
    asm("cvt.rna.tf32.f32 %0, %1;" : "=r"(r) : "f"(x));
    return r;
}

// logical column -> physical column (gate-interleaved map used by the epilogue)
__device__ __forceinline__ int phys_col(int Lp) {
    int ch = Lp >> 7;
    int l  = Lp & 127;
    return ((l & 3) << 8) + (ch << 5) + (l >> 2);   // gate*256 + ch*32 + local_unit
}

__global__ void pack_kernel(const float* __restrict__ W,
                            const float* __restrict__ U,
                            const float* __restrict__ b) {
    int idx = blockIdx.x * blockDim.x + threadIdx.x;   // 0 .. 65535
    if (idx < 16 * NCOLS * 4) {
        int q   = idx & 3;
        int Lp  = (idx >> 2) & (NCOLS - 1);
        int ko2 = idx >> 12;
        int p   = phys_col(Lp);
        int k   = ko2 * 16 + q;
        g_Up[idx] = make_uint4(cvt_tf32(U[(k     ) * NCOLS + p]),
                               cvt_tf32(U[(k +  4) * NCOLS + p]),
                               cvt_tf32(U[(k +  8) * NCOLS + p]),
                               cvt_tf32(U[(k + 12) * NCOLS + p]));
    }
    if (idx < 4 * NCOLS * 4) {
        int q   = idx & 3;
        int Lp  = (idx >> 2) & (NCOLS - 1);
        int ko2 = idx >> 12;
        int p   = phys_col(Lp);
        int k   = ko2 * 16 + q;
        unsigned v0 = (k      < F_IN) ? cvt_tf32(W[(k     ) * NCOLS + p]) : 0u;
        unsigned v1 = (k +  4 < F_IN) ? cvt_tf32(W[(k +  4) * NCOLS + p]) : 0u;
        unsigned v2 = (k +  8 < F_IN) ? cvt_tf32(W[(k +  8) * NCOLS + p]) : 0u;
        unsigned v3 = (k + 12 < F_IN) ? cvt_tf32(W[(k + 12) * NCOLS + p]) : 0u;
        g_Wp[idx] = make_uint4(v0, v1, v2, v3);
    }
    if (idx < NCOLS) {
        g_bp[idx] = b[phys_col(idx)];
    }
}

__device__ __forceinline__ void mma8(float (&c)[4], const unsigned (&a)[4],
                                     unsigned b0, unsigned b1) {
    asm volatile(
        "mma.sync.aligned.m16n8k8.row.col.f32.tf32.tf32.f32 "
        "{%0,%1,%2,%3}, {%4,%5,%6,%7}, {%8,%9}, {%0,%1,%2,%3};\n"
        : "+f"(c[0]), "+f"(c[1]), "+f"(c[2]), "+f"(c[3])
        : "r"(a[0]), "r"(a[1]), "r"(a[2]), "r"(a[3]), "r"(b0), "r"(b1));
}

__device__ __forceinline__ float sigmoidf_(float x) {
    return __fdividef(1.0f, 1.0f + __expf(-x));
}
__device__ __forceinline__ float tanhf_(float x) {
    return 1.0f - __fdividef(2.0f, __expf(2.0f * x) + 1.0f);
}

// acc[mt][cp][nt] += A[64 x KOT2*16](tf32, smem) * Bp for TWO adjacent chunks (cp=0,1).
// A fragments are loaded once per ko2 and reused across both chunks (halves A smem traffic).
// B: ring buffer, PDIST=2 (consume bbuf[ko2&1], then reload it for ko2+2).
template <int KOT2>
__device__ __forceinline__ void gemm_phase2(
    float (&acc)[2][2][4][4], const float* __restrict__ As, int aStride,
    const uint4* __restrict__ Bp, int idxBase, int wm, int lane)
{
    const int q  = lane & 3;
    const int rA = lane >> 2;
    const int arowBase = wm * 32 + rA;

    uint4 bbuf[2][2][4];
    #pragma unroll
    for (int p = 0; p < 2 && p < KOT2; ++p)
        #pragma unroll
        for (int cp = 0; cp < 2; ++cp)
            #pragma unroll
            for (int nt = 0; nt < 4; ++nt)
                bbuf[p][cp][nt] = Bp[idxBase + p * 4096 + cp * 512 + nt * 32];

    #pragma unroll
    for (int ko2 = 0; ko2 < KOT2; ++ko2) {
        const int p = ko2 & 1;

        unsigned a0[2][4], a1[2][4];
        #pragma unroll
        for (int mt = 0; mt < 2; ++mt) {
            const float* ap = As + (arowBase + mt * 16) * aStride + ko2 * 16 + q;
            a0[mt][0] = __float_as_uint(ap[0]);
            a0[mt][1] = __float_as_uint(ap[8 * aStride]);
            a0[mt][2] = __float_as_uint(ap[4]);
            a0[mt][3] = __float_as_uint(ap[8 * aStride + 4]);
            a1[mt][0] = __float_as_uint(ap[8]);
            a1[mt][1] = __float_as_uint(ap[8 * aStride + 8]);
            a1[mt][2] = __float_as_uint(ap[12]);
            a1[mt][3] = __float_as_uint(ap[8 * aStride + 12]);
        }

        #pragma unroll
        for (int cp = 0; cp < 2; ++cp) {
            #pragma unroll
            for (int nt = 0; nt < 4; ++nt) {
                uint4 b = bbuf[p][cp][nt];
                mma8(acc[0][cp][nt], a0[0], b.x, b.y);
                mma8(acc[1][cp][nt], a0[1], b.x, b.y);
                mma8(acc[0][cp][nt], a1[0], b.z, b.w);
                mma8(acc[1][cp][nt], a1[1], b.z, b.w);
            }
        }

        if (ko2 + 2 < KOT2) {
            #pragma unroll
            for (int cp = 0; cp < 2; ++cp)
                #pragma unroll
                for (int nt = 0; nt < 4; ++nt)
                    bbuf[p][cp][nt] = Bp[idxBase + (ko2 + 2) * 4096 + cp * 512 + nt * 32];
        }
    }
}

__global__ void __launch_bounds__(NTHREADS, 1)
lstm_enc_kernel(const float* __restrict__ xg, float* __restrict__ out)
{
    extern __shared__ float smem[];
    float* xs = smem;                              // [BM][SX]
    float* hs = smem + BM * SX;                    // [2][BM][SH] double buffered
    float* cs = smem + BM * SX + 2 * BM * SH;      // [BM][SC] cell state

    const int tid  = threadIdx.x;
    const int lane = tid & 31;
    const int warp = tid >> 5;
    const int wm   = warp >> 2;
    const int wn   = warp & 3;
    const int q    = lane & 3;
    const int rA   = lane >> 2;
    const int row0 = blockIdx.x * BM;
    const bool evenT = ((lane & 1) == 0);

    for (int idx = tid; idx < BM * SC; idx += NTHREADS) cs[idx] = 0.0f;

    for (int t = 0; t < T_STEPS; ++t) {
        __syncthreads();

        // stage x_t (tf32-rounded), zero-pad cols 60..63
        for (int idx = tid; idx < BM * F_IN; idx += NTHREADS) {
            int row = idx / F_IN;
            int col = idx - row * F_IN;
            float v = xg[(size_t)(row0 + row) * (T_STEPS * F_IN) + t * F_IN + col];
            xs[row * SX + col] = __uint_as_float(cvt_tf32(v));
        }
        for (int idx = tid; idx < BM * 4; idx += NTHREADS) {
            int row = idx >> 2;
            xs[row * SX + 60 + (idx & 3)] = 0.0f;
        }
        __syncthreads();

        const int rb = t & 1, wb = rb ^ 1;
        const float* hrd = hs + rb * (BM * SH);
        float*       hwr = hs + wb * (BM * SH);

        // 4 chunk-pairs; each warp covers 32 rows x 64 logical cols (2 chunks x 4 nt)
        for (int ch2 = 0; ch2 < 4; ++ch2) {
            const int idxBase = ((ch2 * 256 + wn * 32 + rA) << 2) + q;

            float acc[2][2][4][4];
            const float2* bp2 = reinterpret_cast<const float2*>(g_bp);
            #pragma unroll
            for (int cp = 0; cp < 2; ++cp) {
                const int ch = ch2 * 2 + cp;
                #pragma unroll
                for (int nt = 0; nt < 4; ++nt) {
                    float2 bb = bp2[ch * 64 + wn * 16 + nt * 4 + q];
                    acc[0][cp][nt][0] = bb.x; acc[0][cp][nt][1] = bb.y;
                    acc[0][cp][nt][2] = bb.x; acc[0][cp][nt][3] = bb.y;
                    acc[1][cp][nt][0] = bb.x; acc[1][cp][nt][1] = bb.y;
                    acc[1][cp][nt][2] = bb.x; acc[1][cp][nt][3] = bb.y;
                }
            }

            gemm_phase2<4>(acc, xs, SX, g_Wp, idxBase, wm, lane);
            if (t > 0)
                gemm_phase2<16>(acc, hrd, SH, g_Up, idxBase, wm, lane);

            // epilogue: gates -> c,h update, per chunk
            #pragma unroll
            for (int cp = 0; cp < 2; ++cp) {
                const int u_base = (ch2 * 2 + cp) * 32;
                #pragma unroll
                for (int mt = 0; mt < 2; ++mt) {
                    const int rowL = wm * 32 + mt * 16 + rA;
                    #pragma unroll
                    for (int nt = 0; nt < 4; ++nt) {
                        const int unit = u_base + wn * 8 + nt * 2 + (q >> 1);
                        float z0 = acc[mt][cp][nt][0], z1 = acc[mt][cp][nt][1];
                        float z2 = acc[mt][cp][nt][2], z3 = acc[mt][cp][nt][3];
                        float p0 = __shfl_xor_sync(0xffffffffu, z0, 1);
                        float p2 = __shfl_xor_sync(0xffffffffu, z2, 1);
                        float tc0 = 0.0f, tc1 = 0.0f;
                        float cn0 = 0.0f, cn1 = 0.0f;
                        if (evenT) {
                            float c0 = cs[rowL * SC + unit];
                            float c1 = cs[(rowL + 8) * SC + unit];
                            float i0 = sigmoidf_(z0), f0 = sigmoidf_(z1), g0 = tanhf_(p0);
                            cn0 = f0 * c0 + i0 * g0;
                            tc0 = tanhf_(cn0);
                            float i1 = sigmoidf_(z2), f1 = sigmoidf_(z3), g1 = tanhf_(p2);
                            cn1 = f1 * c1 + i1 * g1;
                            tc1 = tanhf_(cn1);
                            cs[rowL * SC + unit]       = cn0;
                            cs[(rowL + 8) * SC + unit] = cn1;
                        }
                        float th0 = __shfl_xor_sync(0xffffffffu, tc0, 1);
                        float th1 = __shfl_xor_sync(0xffffffffu, tc1, 1);
                        if (!evenT) {
                            float o0 = sigmoidf_(z1), o1 = sigmoidf_(z3);
                            float h0 = o0 * th0, h1 = o1 * th1;
                            hwr[rowL * SH + unit]       = __uint_as_float(cvt_tf32(h0));
                            hwr[(rowL + 8) * SH + unit] = __uint_as_float(cvt_tf32(h1));
                            if (t == T_STEPS - 1) {
                                size_t g0i = (size_t)(row0 + rowL) * UNITS + unit;
                                size_t g1i = (size_t)(row0 + rowL + 8) * UNITS + unit;
                                const size_t HOFF = (size_t)B_TOTAL * UNITS;
                                out[g0i] = h0;          out[g1i] = h1;
                                out[HOFF + g0i] = h0;   out[HOFF + g1i] = h1;
                            }
                        } else if (t == T_STEPS - 1) {
                            const size_t COFF = 2 * (size_t)B_TOTAL * UNITS;
                            out[COFF + (size_t)(row0 + rowL) * UNITS + unit]     = cn0;
                            out[COFF + (size_t)(row0 + rowL + 8) * UNITS + unit] = cn1;
                        }
                    }
                }
            }
        }
    }
}

extern "C" void kernel_launch(void* const* d_in, const int* in_sizes, int n_in,
                              void* d_out, int out_size) {
    const float* x = nullptr;
    const float* W = nullptr;
    const float* U = nullptr;
    const float* b = nullptr;
    for (int i = 0; i < n_in; ++i) {
        switch (in_sizes[i]) {
            case B_TOTAL * T_STEPS * F_IN: x = (const float*)d_in[i]; break;
            case F_IN * NCOLS:             W = (const float*)d_in[i]; break;
            case UNITS * NCOLS:            U = (const float*)d_in[i]; break;
            case NCOLS:                    b = (const float*)d_in[i]; break;
            default: break;
        }
    }
    if (!x) x = (const float*)d_in[0];
    if (!W) W = (const float*)d_in[1];
    if (!U) U = (const float*)d_in[2];
    if (!b) b = (const float*)d_in[3];

    float* out = (float*)d_out;

    pack_kernel<<<256, 256>>>(W, U, b);

    const int smem_bytes = (BM * SX + 2 * BM * SH + BM * SC) * (int)sizeof(float); // 216320
    cudaFuncSetAttribute(lstm_enc_kernel,
                         cudaFuncAttributeMaxDynamicSharedMemorySize, smem_bytes);
    lstm_enc_kernel<<<B_TOTAL / BM, NTHREADS, smem_bytes>>>(x, out);
}

// round 7
// speedup vs baseline: 5.2597x; 1.2487x over previous
#include <cuda_runtime.h>
#include <cuda_fp16.h>

#define B_TOTAL   131072
#define T_STEPS   7
#define F_IN      60
#define UNITS     256
#define NCOLS     1024      // 4 * UNITS
#define BM        64        // batch rows per CTA
#define SXH       80        // x smem row stride in halves; 160B = 40 words, 40%32==8 -> LDS.64 phase-clean
#define SHH       272       // h smem row stride in halves; 544B = 136 words, 136%32==8 -> LDS.64 phase-clean
#define SC        257       // c smem row stride (fp32)
#define NTHREADS  512       // 16 warps: 2 (M) x 8 (N)

// Packed, fragment-ordered tf32 weights.
// Index: (ko2 * 1024 + Lp) * 4 + q -> uint4{ b(k), b(k+4), b(k+8), b(k+12) }, k = ko2*16+q.
__device__ uint4 g_Wp[4  * NCOLS * 4];   // 256 KB (K padded 60 -> 64 with zeros)
__device__ uint4 g_Up[16 * NCOLS * 4];   // 1 MB
__device__ float g_bp[NCOLS];            // bias permuted to logical order

__device__ __forceinline__ unsigned cvt_tf32(float x) {
    unsigned r;
    asm("cvt.rna.tf32.f32 %0, %1;" : "=r"(r) : "f"(x));
    return r;
}

// logical column -> physical column (gate-interleaved map used by the epilogue)
__device__ __forceinline__ int phys_col(int Lp) {
    int ch = Lp >> 7;
    int l  = Lp & 127;
    return ((l & 3) << 8) + (ch << 5) + (l >> 2);   // gate*256 + ch*32 + local_unit
}

// k (0..K-1) -> packed position within A smem row (fragment-friendly):
// pos = block*16 + (k&3)*4 + ((k>>2)&3), so thread q reads {q, q+4, q+8, q+12} as one 8B load.
__device__ __forceinline__ int kpos(int k) {
    return (k >> 4) * 16 + (k & 3) * 4 + ((k >> 2) & 3);
}

__global__ void pack_kernel(const float* __restrict__ W,
                            const float* __restrict__ U,
                            const float* __restrict__ b) {
    int idx = blockIdx.x * blockDim.x + threadIdx.x;   // 0 .. 65535
    if (idx < 16 * NCOLS * 4) {
        int q   = idx & 3;
        int Lp  = (idx >> 2) & (NCOLS - 1);
        int ko2 = idx >> 12;
        int p   = phys_col(Lp);
        int k   = ko2 * 16 + q;
        g_Up[idx] = make_uint4(cvt_tf32(U[(k     ) * NCOLS + p]),
                               cvt_tf32(U[(k +  4) * NCOLS + p]),
                               cvt_tf32(U[(k +  8) * NCOLS + p]),
                               cvt_tf32(U[(k + 12) * NCOLS + p]));
    }
    if (idx < 4 * NCOLS * 4) {
        int q   = idx & 3;
        int Lp  = (idx >> 2) & (NCOLS - 1);
        int ko2 = idx >> 12;
        int p   = phys_col(Lp);
        int k   = ko2 * 16 + q;
        unsigned v0 = (k      < F_IN) ? cvt_tf32(W[(k     ) * NCOLS + p]) : 0u;
        unsigned v1 = (k +  4 < F_IN) ? cvt_tf32(W[(k +  4) * NCOLS + p]) : 0u;
        unsigned v2 = (k +  8 < F_IN) ? cvt_tf32(W[(k +  8) * NCOLS + p]) : 0u;
        unsigned v3 = (k + 12 < F_IN) ? cvt_tf32(W[(k + 12) * NCOLS + p]) : 0u;
        g_Wp[idx] = make_uint4(v0, v1, v2, v3);
    }
    if (idx < NCOLS) {
        g_bp[idx] = b[phys_col(idx)];
    }
}

__device__ __forceinline__ void mma8(float (&c)[4], const unsigned (&a)[4],
                                     unsigned b0, unsigned b1) {
    asm volatile(
        "mma.sync.aligned.m16n8k8.row.col.f32.tf32.tf32.f32 "
        "{%0,%1,%2,%3}, {%4,%5,%6,%7}, {%8,%9}, {%0,%1,%2,%3};\n"
        : "+f"(c[0]), "+f"(c[1]), "+f"(c[2]), "+f"(c[3])
        : "r"(a[0]), "r"(a[1]), "r"(a[2]), "r"(a[3]), "r"(b0), "r"(b1));
}

__device__ __forceinline__ float sigmoidf_(float x) {
    return __fdividef(1.0f, 1.0f + __expf(-x));
}
__device__ __forceinline__ float tanhf_(float x) {
    return 1.0f - __fdividef(2.0f, __expf(2.0f * x) + 1.0f);
}

// acc[mt][cp][nt] += A[64 x KOT2*16](fp16 packed, smem) * Bp (tf32, LDG.128, PDIST=2 ring)
// for TWO adjacent chunks (cp) and 2 n-tiles each. A fragments loaded once per ko2 via LDS.64.
template <int KOT2>
__device__ __forceinline__ void gemm_phase2(
    float (&acc)[2][2][2][4], const __half* __restrict__ As, int aStride,
    const uint4* __restrict__ Bp, int idxBase, int wm, int lane)
{
    const int q  = lane & 3;
    const int rA = lane >> 2;
    const int arowBase = wm * 32 + rA;

    uint4 bbuf[2][2][2];
    #pragma unroll
    for (int p = 0; p < 2 && p < KOT2; ++p)
        #pragma unroll
        for (int cp = 0; cp < 2; ++cp)
            #pragma unroll
            for (int nt = 0; nt < 2; ++nt)
                bbuf[p][cp][nt] = Bp[idxBase + p * 4096 + cp * 512 + nt * 32];

    #pragma unroll
    for (int ko2 = 0; ko2 < KOT2; ++ko2) {
        const int p = ko2 & 1;

        unsigned a0[2][4], a1[2][4];
        #pragma unroll
        for (int mt = 0; mt < 2; ++mt) {
            const __half* ap = As + (arowBase + mt * 16) * aStride + ko2 * 16 + q * 4;
            uint2 w0 = *reinterpret_cast<const uint2*>(ap);
            uint2 w8 = *reinterpret_cast<const uint2*>(ap + 8 * aStride);
            float2 f;
            f = __half22float2(*reinterpret_cast<__half2*>(&w0.x));
            a0[mt][0] = __float_as_uint(f.x); a0[mt][2] = __float_as_uint(f.y);
            f = __half22float2(*reinterpret_cast<__half2*>(&w0.y));
            a1[mt][0] = __float_as_uint(f.x); a1[mt][2] = __float_as_uint(f.y);
            f = __half22float2(*reinterpret_cast<__half2*>(&w8.x));
            a0[mt][1] = __float_as_uint(f.x); a0[mt][3] = __float_as_uint(f.y);
            f = __half22float2(*reinterpret_cast<__half2*>(&w8.y));
            a1[mt][1] = __float_as_uint(f.x); a1[mt][3] = __float_as_uint(f.y);
        }

        #pragma unroll
        for (int cp = 0; cp < 2; ++cp) {
            #pragma unroll
            for (int nt = 0; nt < 2; ++nt) {
                uint4 b = bbuf[p][cp][nt];
                mma8(acc[0][cp][nt], a0[0], b.x, b.y);
                mma8(acc[1][cp][nt], a0[1], b.x, b.y);
                mma8(acc[0][cp][nt], a1[0], b.z, b.w);
                mma8(acc[1][cp][nt], a1[1], b.z, b.w);
            }
        }

        if (ko2 + 2 < KOT2) {
            #pragma unroll
            for (int cp = 0; cp < 2; ++cp)
                #pragma unroll
                for (int nt = 0; nt < 2; ++nt)
                    bbuf[p][cp][nt] = Bp[idxBase + (ko2 + 2) * 4096 + cp * 512 + nt * 32];
        }
    }
}

__global__ void __launch_bounds__(NTHREADS, 1)
lstm_enc_kernel(const float* __restrict__ xg, float* __restrict__ out)
{
    extern __shared__ char smemc[];
    float*  cs = reinterpret_cast<float*>(smemc);                       // [BM][SC] fp32
    __half* xs = reinterpret_cast<__half*>(smemc + BM * SC * 4);        // [BM][SXH] fp16 packed
    __half* hs = reinterpret_cast<__half*>(smemc + BM * SC * 4 + BM * SXH * 2); // [2][BM][SHH]

    const int tid  = threadIdx.x;
    const int lane = tid & 31;
    const int warp = tid >> 5;
    const int wm   = warp >> 3;       // 0..1 (32 rows each)
    const int wn   = warp & 7;        // 0..7 (16 logical cols per chunk)
    const int q    = lane & 3;
    const int rA   = lane >> 2;
    const int row0 = blockIdx.x * BM;
    const bool evenT = ((lane & 1) == 0);

    for (int idx = tid; idx < BM * SC; idx += NTHREADS) cs[idx] = 0.0f;

    for (int t = 0; t < T_STEPS; ++t) {
        __syncthreads();

        // stage x_t as fp16 (== tf32 rounding), packed layout; zero-pad k=60..63
        for (int idx = tid; idx < BM * F_IN; idx += NTHREADS) {
            int row = idx / F_IN;
            int col = idx - row * F_IN;
            float v = xg[(size_t)(row0 + row) * (T_STEPS * F_IN) + t * F_IN + col];
            xs[row * SXH + kpos(col)] = __float2half_rn(v);
        }
        for (int idx = tid; idx < BM * 4; idx += NTHREADS) {
            int row = idx >> 2;
            xs[row * SXH + kpos(60 + (idx & 3))] = __ushort_as_half(0);
        }
        __syncthreads();

        const int rb = t & 1, wb = rb ^ 1;
        const __half* hrd = hs + rb * (BM * SHH);
        __half*       hwr = hs + wb * (BM * SHH);

        // 4 chunk-pairs; each warp covers 32 rows x 32 logical cols (2 chunks x 2 nt x n8)
        for (int ch2 = 0; ch2 < 4; ++ch2) {
            const int idxBase = ((ch2 * 256 + wn * 16 + rA) << 2) + q;

            float acc[2][2][2][4];
            const float2* bp2 = reinterpret_cast<const float2*>(g_bp);
            #pragma unroll
            for (int cp = 0; cp < 2; ++cp) {
                const int ch = ch2 * 2 + cp;
                #pragma unroll
                for (int nt = 0; nt < 2; ++nt) {
                    float2 bb = bp2[ch * 64 + wn * 8 + nt * 4 + q];
                    acc[0][cp][nt][0] = bb.x; acc[0][cp][nt][1] = bb.y;
                    acc[0][cp][nt][2] = bb.x; acc[0][cp][nt][3] = bb.y;
                    acc[1][cp][nt][0] = bb.x; acc[1][cp][nt][1] = bb.y;
                    acc[1][cp][nt][2] = bb.x; acc[1][cp][nt][3] = bb.y;
                }
            }

            gemm_phase2<4>(acc, xs, SXH, g_Wp, idxBase, wm, lane);
            if (t > 0)
                gemm_phase2<16>(acc, hrd, SHH, g_Up, idxBase, wm, lane);

            // epilogue: gates -> c,h update
            #pragma unroll
            for (int cp = 0; cp < 2; ++cp) {
                const int u_base = (ch2 * 2 + cp) * 32;
                #pragma unroll
                for (int mt = 0; mt < 2; ++mt) {
                    const int rowL = wm * 32 + mt * 16 + rA;
                    #pragma unroll
                    for (int nt = 0; nt < 2; ++nt) {
                        const int unit = u_base + wn * 4 + nt * 2 + (q >> 1);
                        float z0 = acc[mt][cp][nt][0], z1 = acc[mt][cp][nt][1];
                        float z2 = acc[mt][cp][nt][2], z3 = acc[mt][cp][nt][3];
                        float p0 = __shfl_xor_sync(0xffffffffu, z0, 1);
                        float p2 = __shfl_xor_sync(0xffffffffu, z2, 1);
                        float tc0 = 0.0f, tc1 = 0.0f;
                        float cn0 = 0.0f, cn1 = 0.0f;
                        if (evenT) {
                            float c0 = cs[rowL * SC + unit];
                            float c1 = cs[(rowL + 8) * SC + unit];
                            float i0 = sigmoidf_(z0), f0 = sigmoidf_(z1), g0 = tanhf_(p0);
                            cn0 = f0 * c0 + i0 * g0;
                            tc0 = tanhf_(cn0);
                            float i1 = sigmoidf_(z2), f1 = sigmoidf_(z3), g1 = tanhf_(p2);
                            cn1 = f1 * c1 + i1 * g1;
                            tc1 = tanhf_(cn1);
                            cs[rowL * SC + unit]       = cn0;
                            cs[(rowL + 8) * SC + unit] = cn1;
                        }
                        float th0 = __shfl_xor_sync(0xffffffffu, tc0, 1);
                        float th1 = __shfl_xor_sync(0xffffffffu, tc1, 1);
                        if (!evenT) {
                            float o0 = sigmoidf_(z1), o1 = sigmoidf_(z3);
                            float h0 = o0 * th0, h1 = o1 * th1;
                            const int kp = kpos(unit);
                            hwr[rowL * SHH + kp]       = __float2half_rn(h0);
                            hwr[(rowL + 8) * SHH + kp] = __float2half_rn(h1);
                            if (t == T_STEPS - 1) {
                                size_t g0i = (size_t)(row0 + rowL) * UNITS + unit;
                                size_t g1i = (size_t)(row0 + rowL + 8) * UNITS + unit;
                                const size_t HOFF = (size_t)B_TOTAL * UNITS;
                                out[g0i] = h0;          out[g1i] = h1;
                                out[HOFF + g0i] = h0;   out[HOFF + g1i] = h1;
                            }
                        } else if (t == T_STEPS - 1) {
                            const size_t COFF = 2 * (size_t)B_TOTAL * UNITS;
                            out[COFF + (size_t)(row0 + rowL) * UNITS + unit]     = cn0;
                            out[COFF + (size_t)(row0 + rowL + 8) * UNITS + unit] = cn1;
                        }
                    }
                }
            }
        }
    }
}

extern "C" void kernel_launch(void* const* d_in, const int* in_sizes, int n_in,
                              void* d_out, int out_size) {
    const float* x = nullptr;
    const float* W = nullptr;
    const float* U = nullptr;
    const float* b = nullptr;
    for (int i = 0; i < n_in; ++i) {
        switch (in_sizes[i]) {
            case B_TOTAL * T_STEPS * F_IN: x = (const float*)d_in[i]; break;
            case F_IN * NCOLS:             W = (const float*)d_in[i]; break;
            case UNITS * NCOLS:            U = (const float*)d_in[i]; break;
            case NCOLS:                    b = (const float*)d_in[i]; break;
            default: break;
        }
    }
    if (!x) x = (const float*)d_in[0];
    if (!W) W = (const float*)d_in[1];
    if (!U) U = (const float*)d_in[2];
    if (!b) b = (const float*)d_in[3];

    float* out = (float*)d_out;

    pack_kernel<<<256, 256>>>(W, U, b);

    // smem: c fp32 [64][257] + x fp16 [64][80] + h fp16 [2][64][272]  = 145664 B
    const int smem_bytes = BM * SC * 4 + BM * SXH * 2 + 2 * BM * SHH * 2;
    cudaFuncSetAttribute(lstm_enc_kernel,
                         cudaFuncAttributeMaxDynamicSharedMemorySize, smem_bytes);
    lstm_enc_kernel<<<B_TOTAL / BM, NTHREADS, smem_bytes>>>(x, out);
}

// round 8
// speedup vs baseline: 6.3894x; 1.2148x over previous
#include <cuda_runtime.h>
#include <cuda_fp16.h>

#define B_TOTAL   131072
#define T_STEPS   7
#define F_IN      60
#define UNITS     256
#define NCOLS     1024      // 4 * UNITS
#define BM        64        // batch rows per CTA
#define SXH       80        // x smem row stride in halves (conflict-free LDS.64 phases)
#define SHH       272       // h smem row stride in halves (conflict-free LDS.64 phases)
#define SC        257       // c smem row stride (fp32)
#define NTHREADS  512       // 16 warps: 2 (M) x 8 (N)

// Packed fp16 weights, m16n8k16-fragment-ordered.
// Index: (ko4 * 1024 + Lp) * 4 + q -> uint4 of 8 halves covering k = ko4*32 .. +31 for column Lp:
//   .x = h2(k0+2q,  k0+2q+1)   (blk0 b0)      .y = h2(k0+2q+8,  k0+2q+9)   (blk0 b1)
//   .z = h2(k0+16+2q, +17)     (blk1 b0)      .w = h2(k0+24+2q, +25)       (blk1 b1)
__device__ uint4 g_Wp[2 * NCOLS * 4];   // 128 KB (K padded 60 -> 64)
__device__ uint4 g_Up[8 * NCOLS * 4];   // 512 KB
__device__ float g_bp[NCOLS];           // bias permuted to logical order

// logical column -> physical column (gate-interleaved map used by the epilogue)
__device__ __forceinline__ int phys_col(int Lp) {
    int ch = Lp >> 7;
    int l  = Lp & 127;
    return ((l & 3) << 8) + (ch << 5) + (l >> 2);   // gate*256 + ch*32 + local_unit
}

// k -> packed position in A smem row: thread q reads {2q,2q+1,2q+8,2q+9} of each k16
// block as one LDS.64 at offset blk*16 + 4q.
__device__ __forceinline__ int kpos16(int k) {
    return (k >> 4) * 16 + ((k & 7) >> 1) * 4 + ((k >> 3) & 1) * 2 + (k & 1);
}

__device__ __forceinline__ unsigned h2u(float a, float b) {
    __half2 h = __floats2half2_rn(a, b);
    return *reinterpret_cast<unsigned*>(&h);
}

__global__ void pack_kernel(const float* __restrict__ W,
                            const float* __restrict__ U,
                            const float* __restrict__ b) {
    int idx = blockIdx.x * blockDim.x + threadIdx.x;   // 0 .. 32767
    if (idx < 8 * NCOLS * 4) {
        int q   = idx & 3;
        int Lp  = (idx >> 2) & (NCOLS - 1);
        int ko4 = idx >> 12;
        int p   = phys_col(Lp);
        int k0  = ko4 * 32 + 2 * q;
        g_Up[idx] = make_uint4(
            h2u(U[(k0     ) * NCOLS + p], U[(k0 +  1) * NCOLS + p]),
            h2u(U[(k0 +  8) * NCOLS + p], U[(k0 +  9) * NCOLS + p]),
            h2u(U[(k0 + 16) * NCOLS + p], U[(k0 + 17) * NCOLS + p]),
            h2u(U[(k0 + 24) * NCOLS + p], U[(k0 + 25) * NCOLS + p]));
    }
    if (idx < 2 * NCOLS * 4) {
        int q   = idx & 3;
        int Lp  = (idx >> 2) & (NCOLS - 1);
        int ko4 = idx >> 12;
        int p   = phys_col(Lp);
        int k0  = ko4 * 32 + 2 * q;
        #define WV(kk) (((kk) < F_IN) ? W[(kk) * NCOLS + p] : 0.0f)
        g_Wp[idx] = make_uint4(
            h2u(WV(k0),      WV(k0 +  1)),
            h2u(WV(k0 +  8), WV(k0 +  9)),
            h2u(WV(k0 + 16), WV(k0 + 17)),
            h2u(WV(k0 + 24), WV(k0 + 25)));
        #undef WV
    }
    if (idx < NCOLS) {
        g_bp[idx] = b[phys_col(idx)];
    }
}

__device__ __forceinline__ void mma16(float (&c)[4], const unsigned (&a)[4],
                                      unsigned b0, unsigned b1) {
    asm volatile(
        "mma.sync.aligned.m16n8k16.row.col.f32.f16.f16.f32 "
        "{%0,%1,%2,%3}, {%4,%5,%6,%7}, {%8,%9}, {%0,%1,%2,%3};\n"
        : "+f"(c[0]), "+f"(c[1]), "+f"(c[2]), "+f"(c[3])
        : "r"(a[0]), "r"(a[1]), "r"(a[2]), "r"(a[3]), "r"(b0), "r"(b1));
}

__device__ __forceinline__ float sigmoidf_(float x) {
    return __fdividef(1.0f, 1.0f + __expf(-x));
}
__device__ __forceinline__ float tanhf_(float x) {
    return 1.0f - __fdividef(2.0f, __expf(2.0f * x) + 1.0f);
}

// acc[mt][cp][nt] += A[64 x KOT4*32](fp16 packed, smem) * Bp (fp16 packed, LDG.128, PDIST=2)
template <int KOT4>
__device__ __forceinline__ void gemm16(
    float (&acc)[2][2][2][4], const __half* __restrict__ As, int aStride,
    const uint4* __restrict__ Bp, int idxBase, int wm, int lane)
{
    const int q  = lane & 3;
    const int rA = lane >> 2;
    const int arowBase = wm * 32 + rA;

    uint4 bbuf[2][2][2];
    #pragma unroll
    for (int p = 0; p < 2 && p < KOT4; ++p)
        #pragma unroll
        for (int cp = 0; cp < 2; ++cp)
            #pragma unroll
            for (int nt = 0; nt < 2; ++nt)
                bbuf[p][cp][nt] = Bp[idxBase + p * 4096 + cp * 512 + nt * 32];

    #pragma unroll
    for (int ko4 = 0; ko4 < KOT4; ++ko4) {
        const int p = ko4 & 1;

        // A fragments for the two k16 blocks of this k32 (pure LDS.64, no cvt)
        unsigned a[2][2][4];   // [blk][mt][frag]
        #pragma unroll
        for (int mt = 0; mt < 2; ++mt) {
            const __half* ap = As + (arowBase + mt * 16) * aStride + ko4 * 32 + q * 4;
            uint2 w0 = *reinterpret_cast<const uint2*>(ap);
            uint2 w8 = *reinterpret_cast<const uint2*>(ap + 8 * aStride);
            uint2 v0 = *reinterpret_cast<const uint2*>(ap + 16);
            uint2 v8 = *reinterpret_cast<const uint2*>(ap + 16 + 8 * aStride);
            a[0][mt][0] = w0.x; a[0][mt][1] = w8.x; a[0][mt][2] = w0.y; a[0][mt][3] = w8.y;
            a[1][mt][0] = v0.x; a[1][mt][1] = v8.x; a[1][mt][2] = v0.y; a[1][mt][3] = v8.y;
        }

        #pragma unroll
        for (int cp = 0; cp < 2; ++cp) {
            #pragma unroll
            for (int nt = 0; nt < 2; ++nt) {
                uint4 b = bbuf[p][cp][nt];
                mma16(acc[0][cp][nt], a[0][0], b.x, b.y);
                mma16(acc[1][cp][nt], a[0][1], b.x, b.y);
                mma16(acc[0][cp][nt], a[1][0], b.z, b.w);
                mma16(acc[1][cp][nt], a[1][1], b.z, b.w);
            }
        }

        if (ko4 + 2 < KOT4) {
            #pragma unroll
            for (int cp = 0; cp < 2; ++cp)
                #pragma unroll
                for (int nt = 0; nt < 2; ++nt)
                    bbuf[p][cp][nt] = Bp[idxBase + (ko4 + 2) * 4096 + cp * 512 + nt * 32];
        }
    }
}

__global__ void __launch_bounds__(NTHREADS, 1)
lstm_enc_kernel(const float* __restrict__ xg, float* __restrict__ out)
{
    extern __shared__ char smemc[];
    float*  cs = reinterpret_cast<float*>(smemc);                               // [BM][SC]
    __half* xs = reinterpret_cast<__half*>(smemc + BM * SC * 4);                // [BM][SXH]
    __half* hs = reinterpret_cast<__half*>(smemc + BM * SC * 4 + BM * SXH * 2); // [2][BM][SHH]

    const int tid  = threadIdx.x;
    const int lane = tid & 31;
    const int warp = tid >> 5;
    const int wm   = warp >> 3;       // 0..1 (32 rows each)
    const int wn   = warp & 7;        // 0..7
    const int q    = lane & 3;
    const int rA   = lane >> 2;
    const int row0 = blockIdx.x * BM;
    const bool evenT = ((lane & 1) == 0);

    for (int idx = tid; idx < BM * SC; idx += NTHREADS) cs[idx] = 0.0f;

    for (int t = 0; t < T_STEPS; ++t) {
        __syncthreads();

        // stage x_t as fp16 packed; zero-pad k=60..63
        for (int idx = tid; idx < BM * F_IN; idx += NTHREADS) {
            int row = idx / F_IN;
            int col = idx - row * F_IN;
            float v = xg[(size_t)(row0 + row) * (T_STEPS * F_IN) + t * F_IN + col];
            xs[row * SXH + kpos16(col)] = __float2half_rn(v);
        }
        for (int idx = tid; idx < BM * 4; idx += NTHREADS) {
            int row = idx >> 2;
            xs[row * SXH + kpos16(60 + (idx & 3))] = __ushort_as_half(0);
        }
        __syncthreads();

        const int rb = t & 1, wb = rb ^ 1;
        const __half* hrd = hs + rb * (BM * SHH);
        __half*       hwr = hs + wb * (BM * SHH);

        for (int ch2 = 0; ch2 < 4; ++ch2) {
            const int idxBase = ((ch2 * 256 + wn * 16 + rA) << 2) + q;

            float acc[2][2][2][4];
            const float2* bp2 = reinterpret_cast<const float2*>(g_bp);
            #pragma unroll
            for (int cp = 0; cp < 2; ++cp) {
                const int ch = ch2 * 2 + cp;
                #pragma unroll
                for (int nt = 0; nt < 2; ++nt) {
                    float2 bb = bp2[ch * 64 + wn * 8 + nt * 4 + q];
                    acc[0][cp][nt][0] = bb.x; acc[0][cp][nt][1] = bb.y;
                    acc[0][cp][nt][2] = bb.x; acc[0][cp][nt][3] = bb.y;
                    acc[1][cp][nt][0] = bb.x; acc[1][cp][nt][1] = bb.y;
                    acc[1][cp][nt][2] = bb.x; acc[1][cp][nt][3] = bb.y;
                }
            }

            gemm16<2>(acc, xs, SXH, g_Wp, idxBase, wm, lane);
            if (t > 0)
                gemm16<8>(acc, hrd, SHH, g_Up, idxBase, wm, lane);

            // epilogue: gates -> c,h update
            #pragma unroll
            for (int cp = 0; cp < 2; ++cp) {
                const int u_base = (ch2 * 2 + cp) * 32;
                #pragma unroll
                for (int mt = 0; mt < 2; ++mt) {
                    const int rowL = wm * 32 + mt * 16 + rA;
                    #pragma unroll
                    for (int nt = 0; nt < 2; ++nt) {
                        const int unit = u_base + wn * 4 + nt * 2 + (q >> 1);
                        float z0 = acc[mt][cp][nt][0], z1 = acc[mt][cp][nt][1];
                        float z2 = acc[mt][cp][nt][2], z3 = acc[mt][cp][nt][3];
                        float p0 = __shfl_xor_sync(0xffffffffu, z0, 1);
                        float p2 = __shfl_xor_sync(0xffffffffu, z2, 1);
                        float tc0 = 0.0f, tc1 = 0.0f;
                        float cn0 = 0.0f, cn1 = 0.0f;
                        if (evenT) {
                            float c0 = cs[rowL * SC + unit];
                            float c1 = cs[(rowL + 8) * SC + unit];
                            float i0 = sigmoidf_(z0), f0 = sigmoidf_(z1), g0 = tanhf_(p0);
                            cn0 = f0 * c0 + i0 * g0;
                            tc0 = tanhf_(cn0);
                            float i1 = sigmoidf_(z2), f1 = sigmoidf_(z3), g1 = tanhf_(p2);
                            cn1 = f1 * c1 + i1 * g1;
                            tc1 = tanhf_(cn1);
                            cs[rowL * SC + unit]       = cn0;
                            cs[(rowL + 8) * SC + unit] = cn1;
                        }
                        float th0 = __shfl_xor_sync(0xffffffffu, tc0, 1);
                        float th1 = __shfl_xor_sync(0xffffffffu, tc1, 1);
                        if (!evenT) {
                            float o0 = sigmoidf_(z1), o1 = sigmoidf_(z3);
                            float h0 = o0 * th0, h1 = o1 * th1;
                            const int kp = kpos16(unit);
                            hwr[rowL * SHH + kp]       = __float2half_rn(h0);
                            hwr[(rowL + 8) * SHH + kp] = __float2half_rn(h1);
                            if (t == T_STEPS - 1) {
                                size_t g0i = (size_t)(row0 + rowL) * UNITS + unit;
                                size_t g1i = (size_t)(row0 + rowL + 8) * UNITS + unit;
                                const size_t HOFF = (size_t)B_TOTAL * UNITS;
                                out[g0i] = h0;          out[g1i] = h1;
                                out[HOFF + g0i] = h0;   out[HOFF + g1i] = h1;
                            }
                        } else if (t == T_STEPS - 1) {
                            const size_t COFF = 2 * (size_t)B_TOTAL * UNITS;
                            out[COFF + (size_t)(row0 + rowL) * UNITS + unit]     = cn0;
                            out[COFF + (size_t)(row0 + rowL + 8) * UNITS + unit] = cn1;
                        }
                    }
                }
            }
        }
    }
}

extern "C" void kernel_launch(void* const* d_in, const int* in_sizes, int n_in,
                              void* d_out, int out_size) {
    const float* x = nullptr;
    const float* W = nullptr;
    const float* U = nullptr;
    const float* b = nullptr;
    for (int i = 0; i < n_in; ++i) {
        switch (in_sizes[i]) {
            case B_TOTAL * T_STEPS * F_IN: x = (const float*)d_in[i]; break;
            case F_IN * NCOLS:             W = (const float*)d_in[i]; break;
            case UNITS * NCOLS:            U = (const float*)d_in[i]; break;
            case NCOLS:                    b = (const float*)d_in[i]; break;
            default: break;
        }
    }
    if (!x) x = (const float*)d_in[0];
    if (!W) W = (const float*)d_in[1];
    if (!U) U = (const float*)d_in[2];
    if (!b) b = (const float*)d_in[3];

    float* out = (float*)d_out;

    pack_kernel<<<128, 256>>>(W, U, b);

    // smem: c fp32 [64][257] + x fp16 [64][80] + h fp16 [2][64][272] = 145664 B
    const int smem_bytes = BM * SC * 4 + BM * SXH * 2 + 2 * BM * SHH * 2;
    cudaFuncSetAttribute(lstm_enc_kernel,
                         cudaFuncAttributeMaxDynamicSharedMemorySize, smem_bytes);
    lstm_enc_kernel<<<B_TOTAL / BM, NTHREADS, smem_bytes>>>(x, out);
}

// round 9
// speedup vs baseline: 8.5915x; 1.3446x over previous
#include <cuda_runtime.h>
#include <cuda_fp16.h>

#define B_TOTAL   131072
#define T_STEPS   7
#define F_IN      60
#define UNITS     256
#define NCOLS     1024      // 4 * UNITS
#define BM        64        // batch rows per CTA
#define SXH       96        // x smem row stride (halves); S/2=48==16 mod 32 -> LDS.128 conflict-free
#define SHH       288       // h smem row stride (halves); S/2=144==16 mod 32 -> LDS.128 conflict-free
#define SC        260       // c smem row stride (fp32); 260%32==4 -> bank == lane, conflict-free
#define NTHREADS  512       // 16 warps: 2 (M) x 8 (N)

// Packed fp16 weights, m16n8k16-fragment-ordered (same B-frag layout as before).
__device__ uint4 g_Wp[2 * NCOLS * 4];   // 128 KB (K padded 60 -> 64)
__device__ uint4 g_Up[8 * NCOLS * 4];   // 512 KB
__device__ float g_bp[NCOLS];           // bias permuted to logical order

// logical column -> physical column.
// Lp = ch*128 + wn*16 + nt*8 + w, w = unit_local*2 + gi; gate = nt*2+gi; unit = ch*32+wn*4+ul.
// Thread q holds C cols 2q,2q+1 of each tile -> all 4 gates of one unit per (nt pair).
__device__ __forceinline__ int phys_col(int Lp) {
    int ch = Lp >> 7;
    int l  = Lp & 127;
    int wn = l >> 4;
    int nt = (l >> 3) & 1;
    int w  = l & 7;
    int gate = nt * 2 + (w & 1);
    int unit = ch * 32 + wn * 4 + (w >> 1);
    return gate * UNITS + unit;
}

// k -> packed position in A smem row. Per 32-k block: group tq=(k&7)>>1 owns 8 contiguous
// halves {2tq,2tq+1, 2tq+8,2tq+9, 16+2tq,16+2tq+1, 16+2tq+8,16+2tq+9} -> one LDS.128/row/k32.
__device__ __forceinline__ int kpos(int k) {
    return (k & ~31) + ((k & 7) >> 1) * 8 + ((k >> 4) & 1) * 4 + ((k >> 3) & 1) * 2 + (k & 1);
}

__device__ __forceinline__ unsigned h2u(float a, float b) {
    __half2 h = __floats2half2_rn(a, b);
    return *reinterpret_cast<unsigned*>(&h);
}

__global__ void pack_kernel(const float* __restrict__ W,
                            const float* __restrict__ U,
                            const float* __restrict__ b) {
    int idx = blockIdx.x * blockDim.x + threadIdx.x;   // 0 .. 32767
    if (idx < 8 * NCOLS * 4) {
        int q   = idx & 3;
        int Lp  = (idx >> 2) & (NCOLS - 1);
        int ko4 = idx >> 12;
        int p   = phys_col(Lp);
        int k0  = ko4 * 32 + 2 * q;
        g_Up[idx] = make_uint4(
            h2u(U[(k0     ) * NCOLS + p], U[(k0 +  1) * NCOLS + p]),
            h2u(U[(k0 +  8) * NCOLS + p], U[(k0 +  9) * NCOLS + p]),
            h2u(U[(k0 + 16) * NCOLS + p], U[(k0 + 17) * NCOLS + p]),
            h2u(U[(k0 + 24) * NCOLS + p], U[(k0 + 25) * NCOLS + p]));
    }
    if (idx < 2 * NCOLS * 4) {
        int q   = idx & 3;
        int Lp  = (idx >> 2) & (NCOLS - 1);
        int ko4 = idx >> 12;
        int p   = phys_col(Lp);
        int k0  = ko4 * 32 + 2 * q;
        #define WV(kk) (((kk) < F_IN) ? W[(kk) * NCOLS + p] : 0.0f)
        g_Wp[idx] = make_uint4(
            h2u(WV(k0),      WV(k0 +  1)),
            h2u(WV(k0 +  8), WV(k0 +  9)),
            h2u(WV(k0 + 16), WV(k0 + 17)),
            h2u(WV(k0 + 24), WV(k0 + 25)));
        #undef WV
    }
    if (idx < NCOLS) {
        g_bp[idx] = b[phys_col(idx)];
    }
}

__device__ __forceinline__ void mma16(float (&c)[4], const unsigned (&a)[4],
                                      unsigned b0, unsigned b1) {
    asm volatile(
        "mma.sync.aligned.m16n8k16.row.col.f32.f16.f16.f32 "
        "{%0,%1,%2,%3}, {%4,%5,%6,%7}, {%8,%9}, {%0,%1,%2,%3};\n"
        : "+f"(c[0]), "+f"(c[1]), "+f"(c[2]), "+f"(c[3])
        : "r"(a[0]), "r"(a[1]), "r"(a[2]), "r"(a[3]), "r"(b0), "r"(b1));
}

__device__ __forceinline__ float sigmoidf_(float x) {
    return __fdividef(1.0f, 1.0f + __expf(-x));
}
__device__ __forceinline__ float tanhf_(float x) {
    return 1.0f - __fdividef(2.0f, __expf(2.0f * x) + 1.0f);
}

// acc[mt][cp][nt] += A[64 x KOT4*32](fp16 packed, smem, LDS.128) * Bp (fp16, LDG.128, PDIST=2)
template <int KOT4>
__device__ __forceinline__ void gemm16(
    float (&acc)[2][2][2][4], const __half* __restrict__ As, int aStride,
    const uint4* __restrict__ Bp, int idxBase, int wm, int lane)
{
    const int q  = lane & 3;
    const int rA = lane >> 2;
    const int arowBase = wm * 32 + rA;

    uint4 bbuf[2][2][2];
    #pragma unroll
    for (int p = 0; p < 2 && p < KOT4; ++p)
        #pragma unroll
        for (int cp = 0; cp < 2; ++cp)
            #pragma unroll
            for (int nt = 0; nt < 2; ++nt)
                bbuf[p][cp][nt] = Bp[idxBase + p * 4096 + cp * 512 + nt * 32];

    #pragma unroll
    for (int ko4 = 0; ko4 < KOT4; ++ko4) {
        const int p = ko4 & 1;

        // A fragments: 4 LDS.128 per ko4 (2 mt x 2 row-halves), conflict-free
        unsigned a[2][2][4];   // [blk][mt][frag]
        #pragma unroll
        for (int mt = 0; mt < 2; ++mt) {
            const __half* ap = As + (arowBase + mt * 16) * aStride + ko4 * 32 + q * 8;
            uint4 lo = *reinterpret_cast<const uint4*>(ap);
            uint4 hi = *reinterpret_cast<const uint4*>(ap + 8 * aStride);
            a[0][mt][0] = lo.x; a[0][mt][1] = hi.x; a[0][mt][2] = lo.y; a[0][mt][3] = hi.y;
            a[1][mt][0] = lo.z; a[1][mt][1] = hi.z; a[1][mt][2] = lo.w; a[1][mt][3] = hi.w;
        }

        #pragma unroll
        for (int cp = 0; cp < 2; ++cp) {
            #pragma unroll
            for (int nt = 0; nt < 2; ++nt) {
                uint4 b = bbuf[p][cp][nt];
                mma16(acc[0][cp][nt], a[0][0], b.x, b.y);
                mma16(acc[1][cp][nt], a[0][1], b.x, b.y);
                mma16(acc[0][cp][nt], a[1][0], b.z, b.w);
                mma16(acc[1][cp][nt], a[1][1], b.z, b.w);
            }
        }

        if (ko4 + 2 < KOT4) {
            #pragma unroll
            for (int cp = 0; cp < 2; ++cp)
                #pragma unroll
                for (int nt = 0; nt < 2; ++nt)
                    bbuf[p][cp][nt] = Bp[idxBase + (ko4 + 2) * 4096 + cp * 512 + nt * 32];
        }
    }
}

__global__ void __launch_bounds__(NTHREADS, 1)
lstm_enc_kernel(const float* __restrict__ xg, float* __restrict__ out)
{
    extern __shared__ char smemc[];
    float*  cs = reinterpret_cast<float*>(smemc);                               // [BM][SC]
    __half* xs = reinterpret_cast<__half*>(smemc + BM * SC * 4);                // [BM][SXH]
    __half* hs = reinterpret_cast<__half*>(smemc + BM * SC * 4 + BM * SXH * 2); // [2][BM][SHH]

    const int tid  = threadIdx.x;
    const int lane = tid & 31;
    const int warp = tid >> 5;
    const int wm   = warp >> 3;       // 0..1 (32 rows each)
    const int wn   = warp & 7;        // 0..7 (4 units per chunk)
    const int q    = lane & 3;
    const int rA   = lane >> 2;
    const int row0 = blockIdx.x * BM;

    for (int idx = tid; idx < BM * SC; idx += NTHREADS) cs[idx] = 0.0f;

    for (int t = 0; t < T_STEPS; ++t) {
        __syncthreads();

        // stage x_t as fp16 packed; zero-pad k=60..63
        for (int idx = tid; idx < BM * F_IN; idx += NTHREADS) {
            int row = idx / F_IN;
            int col = idx - row * F_IN;
            float v = xg[(size_t)(row0 + row) * (T_STEPS * F_IN) + t * F_IN + col];
            xs[row * SXH + kpos(col)] = __float2half_rn(v);
        }
        for (int idx = tid; idx < BM * 4; idx += NTHREADS) {
            int row = idx >> 2;
            xs[row * SXH + kpos(60 + (idx & 3))] = __ushort_as_half(0);
        }
        __syncthreads();

        const int rb = t & 1, wb = rb ^ 1;
        const __half* hrd = hs + rb * (BM * SHH);
        __half*       hwr = hs + wb * (BM * SHH);

        for (int ch2 = 0; ch2 < 4; ++ch2) {
            const int idxBase = ((ch2 * 256 + wn * 16 + rA) << 2) + q;

            float acc[2][2][2][4];
            const float2* bp2 = reinterpret_cast<const float2*>(g_bp);
            #pragma unroll
            for (int cp = 0; cp < 2; ++cp) {
                const int ch = ch2 * 2 + cp;
                #pragma unroll
                for (int nt = 0; nt < 2; ++nt) {
                    float2 bb = bp2[ch * 64 + wn * 8 + nt * 4 + q];
                    acc[0][cp][nt][0] = bb.x; acc[0][cp][nt][1] = bb.y;
                    acc[0][cp][nt][2] = bb.x; acc[0][cp][nt][3] = bb.y;
                    acc[1][cp][nt][0] = bb.x; acc[1][cp][nt][1] = bb.y;
                    acc[1][cp][nt][2] = bb.x; acc[1][cp][nt][3] = bb.y;
                }
            }

            gemm16<2>(acc, xs, SXH, g_Wp, idxBase, wm, lane);
            if (t > 0)
                gemm16<8>(acc, hrd, SHH, g_Up, idxBase, wm, lane);

            // epilogue: thread q owns all 4 gates of unit (wn*4+q), rows rowL & rowL+8.
            #pragma unroll
            for (int cp = 0; cp < 2; ++cp) {
                const int unit = (ch2 * 2 + cp) * 32 + wn * 4 + q;
                const int kp   = kpos(unit);
                #pragma unroll
                for (int mt = 0; mt < 2; ++mt) {
                    const int rowL = wm * 32 + mt * 16 + rA;
                    float zi0 = acc[mt][cp][0][0], zf0 = acc[mt][cp][0][1];
                    float zi1 = acc[mt][cp][0][2], zf1 = acc[mt][cp][0][3];
                    float zg0 = acc[mt][cp][1][0], zo0 = acc[mt][cp][1][1];
                    float zg1 = acc[mt][cp][1][2], zo1 = acc[mt][cp][1][3];

                    float c0 = cs[rowL * SC + unit];
                    float c1 = cs[(rowL + 8) * SC + unit];
                    float cn0 = sigmoidf_(zf0) * c0 + sigmoidf_(zi0) * tanhf_(zg0);
                    float cn1 = sigmoidf_(zf1) * c1 + sigmoidf_(zi1) * tanhf_(zg1);
                    cs[rowL * SC + unit]       = cn0;
                    cs[(rowL + 8) * SC + unit] = cn1;
                    float h0 = sigmoidf_(zo0) * tanhf_(cn0);
                    float h1 = sigmoidf_(zo1) * tanhf_(cn1);

                    hwr[rowL * SHH + kp]       = __float2half_rn(h0);
                    hwr[(rowL + 8) * SHH + kp] = __float2half_rn(h1);

                    if (t == T_STEPS - 1) {
                        size_t g0i = (size_t)(row0 + rowL) * UNITS + unit;
                        size_t g1i = (size_t)(row0 + rowL + 8) * UNITS + unit;
                        const size_t HOFF = (size_t)B_TOTAL * UNITS;
                        const size_t COFF = 2 * HOFF;
                        out[g0i] = h0;          out[g1i] = h1;
                        out[HOFF + g0i] = h0;   out[HOFF + g1i] = h1;
                        out[COFF + g0i] = cn0;  out[COFF + g1i] = cn1;
                    }
                }
            }
        }
    }
}

extern "C" void kernel_launch(void* const* d_in, const int* in_sizes, int n_in,
                              void* d_out, int out_size) {
    const float* x = nullptr;
    const float* W = nullptr;
    const float* U = nullptr;
    const float* b = nullptr;
    for (int i = 0; i < n_in; ++i) {
        switch (in_sizes[i]) {
            case B_TOTAL * T_STEPS * F_IN: x = (const float*)d_in[i]; break;
            case F_IN * NCOLS:             W = (const float*)d_in[i]; break;
            case UNITS * NCOLS:            U = (const float*)d_in[i]; break;
            case NCOLS:                    b = (const float*)d_in[i]; break;
            default: break;
        }
    }
    if (!x) x = (const float*)d_in[0];
    if (!W) W = (const float*)d_in[1];
    if (!U) U = (const float*)d_in[2];
    if (!b) b = (const float*)d_in[3];

    float* out = (float*)d_out;

    pack_kernel<<<128, 256>>>(W, U, b);

    // smem: c fp32 [64][260] + x fp16 [64][96] + h fp16 [2][64][288] = 152576 B
    const int smem_bytes = BM * SC * 4 + BM * SXH * 2 + 2 * BM * SHH * 2;
    cudaFuncSetAttribute(lstm_enc_kernel,
                         cudaFuncAttributeMaxDynamicSharedMemorySize, smem_bytes);
    lstm_enc_kernel<<<B_TOTAL / BM, NTHREADS, smem_bytes>>>(x, out);
}